// round 7
// baseline (speedup 1.0000x reference)
#include <cuda_runtime.h>
#include <cuda_bf16.h>
#include <cstddef>

// Problem constants
#define S_LEN  2048
#define EMB    1024
#define NH     16
#define HD     64
#define BATCH  2
#define MROWS  (BATCH * S_LEN)   // 4096

// Scratch in device globals (no allocation allowed)
__device__ float g_q[(size_t)BATCH * NH * S_LEN * HD];
__device__ float g_k[(size_t)BATCH * NH * S_LEN * HD];
__device__ float g_v[(size_t)BATCH * NH * S_LEN * HD];
__device__ float g_ctx[(size_t)BATCH * S_LEN * EMB];

// ---------------------------------------------------------------------------
// Tiled fp32 GEMM: C[M,N] = A[M,K] @ W[K,N] (+bias)
// M=4096, N=K=1024. BM=BN=128, BK=16, 256 threads, 8x8 per-thread microtile.
// MODE 0: C[row*N+col] = acc + bias[col]           (row-major output)
// MODE 1: write to [B, H, S, D] layout (head split) (no bias)
// ---------------------------------------------------------------------------
template <int MODE>
__global__ __launch_bounds__(256) void gemm_k(const float* __restrict__ A,
                                              const float* __restrict__ W,
                                              const float* __restrict__ bias,
                                              float* __restrict__ C)
{
    const int K = EMB, N = EMB;
    __shared__ float As[16][128];   // transposed A tile: As[k][m]
    __shared__ float Ws[16][128];   // Ws[k][n]

    const int tid = threadIdx.x;
    const int bm = blockIdx.y * 128;
    const int bn = blockIdx.x * 128;
    const int tx = tid & 15;        // 0..15 -> n
    const int ty = tid >> 4;        // 0..15 -> m

    float c[8][8];
#pragma unroll
    for (int i = 0; i < 8; i++)
#pragma unroll
        for (int j = 0; j < 8; j++) c[i][j] = 0.f;

    for (int k0 = 0; k0 < K; k0 += 16) {
        // Load A tile (128 rows x 16 cols), store transposed
#pragma unroll
        for (int i = 0; i < 2; i++) {
            int row = (tid >> 2) + i * 64;       // 0..127
            int kc  = (tid & 3) << 2;            // 0,4,8,12
            float4 a = *(const float4*)(A + (size_t)(bm + row) * K + k0 + kc);
            As[kc + 0][row] = a.x;
            As[kc + 1][row] = a.y;
            As[kc + 2][row] = a.z;
            As[kc + 3][row] = a.w;
        }
        // Load W tile (16 rows x 128 cols)
#pragma unroll
        for (int i = 0; i < 2; i++) {
            int kr = (tid >> 5) + i * 8;         // 0..15
            int nc = (tid & 31) << 2;            // 0..124
            *(float4*)&Ws[kr][nc] =
                *(const float4*)(W + (size_t)(k0 + kr) * N + bn + nc);
        }
        __syncthreads();

#pragma unroll
        for (int k = 0; k < 16; k++) {
            float a[8], b[8];
            *(float4*)(a + 0) = *(float4*)&As[k][(ty << 3) + 0];
            *(float4*)(a + 4) = *(float4*)&As[k][(ty << 3) + 4];
            *(float4*)(b + 0) = *(float4*)&Ws[k][(tx << 3) + 0];
            *(float4*)(b + 4) = *(float4*)&Ws[k][(tx << 3) + 4];
#pragma unroll
            for (int i = 0; i < 8; i++)
#pragma unroll
                for (int j = 0; j < 8; j++) c[i][j] += a[i] * b[j];
        }
        __syncthreads();
    }

    // Epilogue
#pragma unroll
    for (int i = 0; i < 8; i++) {
        int row = bm + (ty << 3) + i;
#pragma unroll
        for (int j = 0; j < 8; j += 4) {
            int col = bn + (tx << 3) + j;
            float4 v;
            v.x = c[i][j + 0];
            v.y = c[i][j + 1];
            v.z = c[i][j + 2];
            v.w = c[i][j + 3];
            if (MODE == 0) {
                v.x += bias[col + 0];
                v.y += bias[col + 1];
                v.z += bias[col + 2];
                v.w += bias[col + 3];
                *(float4*)&C[(size_t)row * N + col] = v;
            } else {
                int b_ = row >> 11;         // row / S_LEN
                int s  = row & (S_LEN - 1);
                int h  = col >> 6;          // col / HD
                int d  = col & (HD - 1);
                size_t off = ((((size_t)b_ * NH + h) * S_LEN) + s) * HD + d;
                *(float4*)&C[off] = v;
            }
        }
    }
}

// ---------------------------------------------------------------------------
// Flash attention (causal), fp32. One thread owns one query row fully.
// Block = 128 threads = 128 query rows. K/V tiles of 32 rows x 64 in SMEM.
// grid = (S/128, B*H)
// ---------------------------------------------------------------------------
__global__ __launch_bounds__(128) void flash_k(const float* __restrict__ Q,
                                               const float* __restrict__ Kg,
                                               const float* __restrict__ Vg,
                                               float* __restrict__ O)
{
    __shared__ float Ks[32][64];
    __shared__ float Vs[32][64];

    const int qt  = blockIdx.x;   // 0..15
    const int bh  = blockIdx.y;   // 0..31
    const int tid = threadIdx.x;
    const int qrow = qt * 128 + tid;

    const float* qp = Q + ((size_t)bh * S_LEN + qrow) * HD;
    float q[64];
#pragma unroll
    for (int i = 0; i < 16; i++)
        *(float4*)&q[i * 4] = *(const float4*)(qp + i * 4);

    float acc[64];
#pragma unroll
    for (int d = 0; d < 64; d++) acc[d] = 0.f;
    float m = -1e30f, l = 0.f;

    const int ntiles = 4 * qt + 4;  // covers keys 0 .. qt*128+127 (causal)
    const float* kbase_p = Kg + (size_t)bh * S_LEN * HD;
    const float* vbase_p = Vg + (size_t)bh * S_LEN * HD;

    for (int kt = 0; kt < ntiles; kt++) {
        __syncthreads();
        // load K,V tiles: 32*64 = 2048 floats each = 512 float4 each
        const float4* ksrc = (const float4*)(kbase_p + (size_t)kt * 32 * 64);
        const float4* vsrc = (const float4*)(vbase_p + (size_t)kt * 32 * 64);
#pragma unroll
        for (int i = 0; i < 4; i++) {
            int idx = tid + i * 128;
            ((float4*)Ks)[idx] = ksrc[idx];
            ((float4*)Vs)[idx] = vsrc[idx];
        }
        __syncthreads();

        const int kb = kt * 32;
        float sc[32];
#pragma unroll
        for (int k = 0; k < 32; k++) {
            float s = 0.f;
#pragma unroll
            for (int d = 0; d < 64; d += 4) {
                float4 kk = *(const float4*)&Ks[k][d];
                s += q[d + 0] * kk.x + q[d + 1] * kk.y +
                     q[d + 2] * kk.z + q[d + 3] * kk.w;
            }
            s *= 0.125f;  // 1/sqrt(64)
            sc[k] = (kb + k > qrow) ? -1e30f : s;
        }

        float mt = m;
#pragma unroll
        for (int k = 0; k < 32; k++) mt = fmaxf(mt, sc[k]);
        float corr = __expf(m - mt);
        float sum = 0.f;
#pragma unroll
        for (int k = 0; k < 32; k++) {
            sc[k] = __expf(sc[k] - mt);
            sum += sc[k];
        }
        l = l * corr + sum;
#pragma unroll
        for (int d = 0; d < 64; d++) acc[d] *= corr;
#pragma unroll
        for (int k = 0; k < 32; k++) {
            float p = sc[k];
#pragma unroll
            for (int d = 0; d < 64; d += 4) {
                float4 vv = *(const float4*)&Vs[k][d];
                acc[d + 0] += p * vv.x;
                acc[d + 1] += p * vv.y;
                acc[d + 2] += p * vv.z;
                acc[d + 3] += p * vv.w;
            }
        }
        m = mt;
    }

    const float inv = 1.f / l;
    const int b_ = bh >> 4;
    const int h  = bh & 15;
    float* op = O + ((size_t)b_ * S_LEN + qrow) * EMB + h * HD;
#pragma unroll
    for (int d = 0; d < 64; d += 4) {
        float4 v;
        v.x = acc[d + 0] * inv;
        v.y = acc[d + 1] * inv;
        v.z = acc[d + 2] * inv;
        v.w = acc[d + 3] * inv;
        *(float4*)(op + d) = v;
    }
}

// ---------------------------------------------------------------------------
extern "C" void kernel_launch(void* const* d_in, const int* in_sizes, int n_in,
                              void* d_out, int out_size)
{
    const float* x  = (const float*)d_in[0];
    const float* Wq = (const float*)d_in[1];
    const float* Wk = (const float*)d_in[2];
    const float* Wv = (const float*)d_in[3];
    const float* Wo = (const float*)d_in[4];
    const float* bo = (const float*)d_in[5];
    float* out = (float*)d_out;

    float *qb, *kb, *vb, *cb;
    cudaGetSymbolAddress((void**)&qb, g_q);
    cudaGetSymbolAddress((void**)&kb, g_k);
    cudaGetSymbolAddress((void**)&vb, g_v);
    cudaGetSymbolAddress((void**)&cb, g_ctx);

    dim3 gg(EMB / 128, MROWS / 128);  // (8, 32)

    gemm_k<1><<<gg, 256>>>(x, Wq, nullptr, qb);
    gemm_k<1><<<gg, 256>>>(x, Wk, nullptr, kb);
    gemm_k<1><<<gg, 256>>>(x, Wv, nullptr, vb);

    flash_k<<<dim3(S_LEN / 128, BATCH * NH), 128>>>(qb, kb, vb, cb);

    gemm_k<0><<<gg, 256>>>(cb, Wo, bo, out);
}

// round 14
// speedup vs baseline: 1.3212x; 1.3212x over previous
#include <cuda_runtime.h>
#include <cuda_bf16.h>
#include <cstdint>
#include <cstddef>

// Problem constants
#define S_LEN  2048
#define EMB    1024
#define NH     16
#define HD     64
#define BATCH  2
#define MROWS  (BATCH * S_LEN)   // 4096

// Scratch in device globals (no allocation allowed)
__device__ float g_q[(size_t)BATCH * NH * S_LEN * HD];
__device__ float g_k[(size_t)BATCH * NH * S_LEN * HD];
__device__ float g_v[(size_t)BATCH * NH * S_LEN * HD];
__device__ float g_ctx[(size_t)BATCH * S_LEN * EMB];
__device__ float g_xt[(size_t)MROWS * EMB];       // x, tf32-rounded
__device__ float g_wt[4ULL * EMB * EMB];          // transposed weights, tf32-rounded

// ---------------------------------------------------------------------------
// Helpers
// ---------------------------------------------------------------------------
__device__ __forceinline__ uint32_t smem_u32(const void* p) {
    uint32_t a;
    asm("{ .reg .u64 t; cvta.to.shared.u64 t, %1; cvt.u32.u64 %0, t; }" : "=r"(a) : "l"(p));
    return a;
}
__device__ __forceinline__ float to_tf32(float x) {
    float y;
    asm("cvt.rna.tf32.f32 %0, %1;" : "=f"(y) : "f"(x));
    return y;
}

#define CP_ASYNC16(sa, gp) \
    asm volatile("cp.async.cg.shared.global [%0], [%1], 16;" :: "r"(sa), "l"(gp) : "memory")
#define CP_COMMIT() asm volatile("cp.async.commit_group;" ::: "memory")
#define CP_WAIT(n)  asm volatile("cp.async.wait_group %0;" :: "n"(n) : "memory")

// m16n8k8 tf32 mma: D += A * B  (A row-major m16k8 frag, B col-major n8k8 frag)
__device__ __forceinline__ void mma1688(float* c, const uint32_t* a, const uint32_t* b) {
    asm volatile(
        "mma.sync.aligned.m16n8k8.row.col.f32.tf32.tf32.f32 "
        "{%0,%1,%2,%3}, {%4,%5,%6,%7}, {%8,%9}, {%0,%1,%2,%3};"
        : "+f"(c[0]), "+f"(c[1]), "+f"(c[2]), "+f"(c[3])
        : "r"(a[0]), "r"(a[1]), "r"(a[2]), "r"(a[3]), "r"(b[0]), "r"(b[1]));
}

// ---------------------------------------------------------------------------
// x -> tf32-rounded copy (one-shot, 4M elements)
// ---------------------------------------------------------------------------
__global__ __launch_bounds__(256) void cvt_tf32_k(const float* __restrict__ in,
                                                  float* __restrict__ out)
{
    int i = blockIdx.x * 256 + threadIdx.x;   // grid covers 1M float4
    float4 v = ((const float4*)in)[i];
    v.x = to_tf32(v.x); v.y = to_tf32(v.y);
    v.z = to_tf32(v.z); v.w = to_tf32(v.w);
    ((float4*)out)[i] = v;
}

// ---------------------------------------------------------------------------
// Weight transpose: WT[n][k] = tf32(W[k][n]); 1024x1024
// ---------------------------------------------------------------------------
__global__ __launch_bounds__(256) void transpose_k(const float* __restrict__ W,
                                                   float* __restrict__ WT)
{
    __shared__ float t[32][33];
    const int bx = blockIdx.x * 32, by = blockIdx.y * 32;
#pragma unroll
    for (int i = threadIdx.y; i < 32; i += 8)
        t[i][threadIdx.x] = W[(size_t)(by + i) * EMB + bx + threadIdx.x];
    __syncthreads();
#pragma unroll
    for (int i = threadIdx.y; i < 32; i += 8)
        WT[(size_t)(bx + i) * EMB + by + threadIdx.x] = to_tf32(t[threadIdx.x][i]);
}

// ---------------------------------------------------------------------------
// mma.sync tf32 GEMM: C[M,N] = A[M,K] @ BT[N,K]^T, all inputs pre-rounded tf32.
// CTA 128x128, BK=32, 256 threads (8 warps as 2x4), warp tile 64x32.
// SMEM layout [row][k] with stride 36 floats (pad) -> conflict-free frag loads.
// Double-buffered cp.async pipeline.
// MODE 0: C[row*N+col] = acc + bias[col]
// MODE 1: headsplit write to [B, H, S, D]
// ---------------------------------------------------------------------------
#define GK_STRIDE 36                       // floats per smem row
#define GK_TILE   (128 * GK_STRIDE * 4)    // bytes per tile stage = 18432
#define GK_SMEM   (4 * GK_TILE)            // 73728: As0, As1, Bs0, Bs1

template <int MODE>
__global__ __launch_bounds__(256, 1) void gemm_tc(const float* __restrict__ A,
                                                  const float* __restrict__ BT,
                                                  const float* __restrict__ bias,
                                                  float* __restrict__ C)
{
    extern __shared__ char smem[];
    const uint32_t smem_base = smem_u32(smem);
    const int tid = threadIdx.x;
    const int wid = tid >> 5;
    const int lane = tid & 31;
    const int grp = lane >> 2;     // 0..7
    const int tig = lane & 3;      // 0..3
    const int bm = blockIdx.y * 128;
    const int bn = blockIdx.x * 128;
    const int wm = (wid >> 2) * 64;    // warp m offset in tile
    const int wn = (wid & 3) * 32;     // warp n offset in tile

    float acc[4][4][4];
#pragma unroll
    for (int mi = 0; mi < 4; mi++)
#pragma unroll
        for (int ni = 0; ni < 4; ni++)
#pragma unroll
            for (int r = 0; r < 4; r++) acc[mi][ni][r] = 0.f;

    // cp.async indices: 1024 float4 per tile / 256 threads = 4 each
    const int crow = tid >> 1;                // 0..127 (2 float4 per thread-row pass)
    const int cq   = (tid & 1) << 1;          // 0 or 2 (float4 index)

    auto stage_a = [&](int st) -> uint32_t { return smem_base + st * GK_TILE; };
    auto stage_b = [&](int st) -> uint32_t { return smem_base + (2 + st) * GK_TILE; };

    auto prefetch = [&](int c) {
        const int k0 = c * 32;
        const uint32_t sa = stage_a(c & 1);
        const uint32_t sb = stage_b(c & 1);
#pragma unroll
        for (int h = 0; h < 2; h++) {
            int q = cq + h;                        // float4 col 0..3 -> covers 16 floats? no: 4 f4 = 16
            // each row has 8 float4 (32 floats); 256 threads cover 128 rows x 2 f4 per pass,
            // need 2 passes over q-halves:
            (void)q;
        }
        // A: rows 0..127, 8 float4 per row = 1024 f4. thread handles rows crow, f4 {cq, cq+1, cq+4, cq+5}
#pragma unroll
        for (int h = 0; h < 2; h++) {
            int q0 = cq + h * 4;                   // 0,1,4,5 or 2,3,6,7
            const float* gp = A + (size_t)(bm + crow) * EMB + k0 + q0 * 4;
            CP_ASYNC16(sa + (uint32_t)(crow * GK_STRIDE + q0 * 4) * 4, gp);
            const float* gq = A + (size_t)(bm + crow) * EMB + k0 + (q0 + 1) * 4;
            CP_ASYNC16(sa + (uint32_t)(crow * GK_STRIDE + (q0 + 1) * 4) * 4, gq);
        }
#pragma unroll
        for (int h = 0; h < 2; h++) {
            int q0 = cq + h * 4;
            const float* gp = BT + (size_t)(bn + crow) * EMB + k0 + q0 * 4;
            CP_ASYNC16(sb + (uint32_t)(crow * GK_STRIDE + q0 * 4) * 4, gp);
            const float* gq = BT + (size_t)(bn + crow) * EMB + k0 + (q0 + 1) * 4;
            CP_ASYNC16(sb + (uint32_t)(crow * GK_STRIDE + (q0 + 1) * 4) * 4, gq);
        }
        CP_COMMIT();
    };

    prefetch(0);

    for (int c = 0; c < 32; ++c) {
        if (c < 31) { prefetch(c + 1); CP_WAIT(1); }
        else        { CP_WAIT(0); }
        __syncthreads();

        const float* as = (const float*)(smem + (size_t)(c & 1) * GK_TILE);
        const float* bs = (const float*)(smem + (size_t)(2 + (c & 1)) * GK_TILE);

#pragma unroll
        for (int kk = 0; kk < 4; kk++) {
            const int kc = kk * 8 + tig;
            uint32_t af[4][4], bf[4][2];
#pragma unroll
            for (int mi = 0; mi < 4; mi++) {
                const float* p = as + (wm + mi * 16 + grp) * GK_STRIDE + kc;
                af[mi][0] = __float_as_uint(p[0]);
                af[mi][1] = __float_as_uint(p[8 * GK_STRIDE]);
                af[mi][2] = __float_as_uint(p[4]);
                af[mi][3] = __float_as_uint(p[8 * GK_STRIDE + 4]);
            }
#pragma unroll
            for (int ni = 0; ni < 4; ni++) {
                const float* p = bs + (wn + ni * 8 + grp) * GK_STRIDE + kc;
                bf[ni][0] = __float_as_uint(p[0]);
                bf[ni][1] = __float_as_uint(p[4]);
            }
#pragma unroll
            for (int mi = 0; mi < 4; mi++)
#pragma unroll
                for (int ni = 0; ni < 4; ni++)
                    mma1688(acc[mi][ni], af[mi], bf[ni]);
        }
        __syncthreads();
    }

    // Epilogue. Thread owns, per (mi,ni): rows wm+mi*16+grp (+8), cols wn+ni*8+tig*2 (+1)
#pragma unroll
    for (int mi = 0; mi < 4; mi++) {
#pragma unroll
        for (int half = 0; half < 2; half++) {
            const int row = bm + wm + mi * 16 + grp + half * 8;
            if (MODE == 0) {
#pragma unroll
                for (int ni = 0; ni < 4; ni++) {
                    const int col = bn + wn + ni * 8 + tig * 2;
                    float2 v;
                    v.x = acc[mi][ni][half * 2 + 0] + bias[col + 0];
                    v.y = acc[mi][ni][half * 2 + 1] + bias[col + 1];
                    *(float2*)&C[(size_t)row * EMB + col] = v;
                }
            } else {
                const int b_ = row >> 11;
                const int sr = row & (S_LEN - 1);
#pragma unroll
                for (int ni = 0; ni < 4; ni++) {
                    const int col = bn + wn + ni * 8 + tig * 2;
                    const int h = col >> 6;
                    const int d = col & (HD - 1);
                    float2 v;
                    v.x = acc[mi][ni][half * 2 + 0];
                    v.y = acc[mi][ni][half * 2 + 1];
                    *(float2*)(C + ((((size_t)b_ * NH + h) * S_LEN) + sr) * HD + d) = v;
                }
            }
        }
    }
}

// ---------------------------------------------------------------------------
// Flash attention (causal), fp32. One thread owns one query row fully.
// Writes ctx tf32-rounded (consumed by the tf32 output GEMM).
// ---------------------------------------------------------------------------
__global__ __launch_bounds__(128) void flash_k(const float* __restrict__ Q,
                                               const float* __restrict__ Kg,
                                               const float* __restrict__ Vg,
                                               float* __restrict__ O)
{
    __shared__ float Ks[32][64];
    __shared__ float Vs[32][64];

    const int qt  = blockIdx.x;
    const int bh  = blockIdx.y;
    const int tid = threadIdx.x;
    const int qrow = qt * 128 + tid;

    const float* qp = Q + ((size_t)bh * S_LEN + qrow) * HD;
    float q[64];
#pragma unroll
    for (int i = 0; i < 16; i++)
        *(float4*)&q[i * 4] = *(const float4*)(qp + i * 4);

    float acc[64];
#pragma unroll
    for (int d = 0; d < 64; d++) acc[d] = 0.f;
    float m = -1e30f, l = 0.f;

    const int ntiles = 4 * qt + 4;
    const float* kbase_p = Kg + (size_t)bh * S_LEN * HD;
    const float* vbase_p = Vg + (size_t)bh * S_LEN * HD;

    for (int kt = 0; kt < ntiles; kt++) {
        __syncthreads();
        const float4* ksrc = (const float4*)(kbase_p + (size_t)kt * 32 * 64);
        const float4* vsrc = (const float4*)(vbase_p + (size_t)kt * 32 * 64);
#pragma unroll
        for (int i = 0; i < 4; i++) {
            int idx = tid + i * 128;
            ((float4*)Ks)[idx] = ksrc[idx];
            ((float4*)Vs)[idx] = vsrc[idx];
        }
        __syncthreads();

        const int kb = kt * 32;
        float sc[32];
#pragma unroll
        for (int k = 0; k < 32; k++) {
            float s = 0.f;
#pragma unroll
            for (int d = 0; d < 64; d += 4) {
                float4 kk = *(const float4*)&Ks[k][d];
                s += q[d + 0] * kk.x + q[d + 1] * kk.y +
                     q[d + 2] * kk.z + q[d + 3] * kk.w;
            }
            s *= 0.125f;
            sc[k] = (kb + k > qrow) ? -1e30f : s;
        }

        float mt = m;
#pragma unroll
        for (int k = 0; k < 32; k++) mt = fmaxf(mt, sc[k]);
        float corr = __expf(m - mt);
        float sum = 0.f;
#pragma unroll
        for (int k = 0; k < 32; k++) {
            sc[k] = __expf(sc[k] - mt);
            sum += sc[k];
        }
        l = l * corr + sum;
#pragma unroll
        for (int d = 0; d < 64; d++) acc[d] *= corr;
#pragma unroll
        for (int k = 0; k < 32; k++) {
            float p = sc[k];
#pragma unroll
            for (int d = 0; d < 64; d += 4) {
                float4 vv = *(const float4*)&Vs[k][d];
                acc[d + 0] += p * vv.x;
                acc[d + 1] += p * vv.y;
                acc[d + 2] += p * vv.z;
                acc[d + 3] += p * vv.w;
            }
        }
        m = mt;
    }

    const float inv = 1.f / l;
    const int b_ = bh >> 4;
    const int h  = bh & 15;
    float* op = O + ((size_t)b_ * S_LEN + qrow) * EMB + h * HD;
#pragma unroll
    for (int d = 0; d < 64; d += 4) {
        float4 v;
        v.x = to_tf32(acc[d + 0] * inv);
        v.y = to_tf32(acc[d + 1] * inv);
        v.z = to_tf32(acc[d + 2] * inv);
        v.w = to_tf32(acc[d + 3] * inv);
        *(float4*)(op + d) = v;
    }
}

// ---------------------------------------------------------------------------
extern "C" void kernel_launch(void* const* d_in, const int* in_sizes, int n_in,
                              void* d_out, int out_size)
{
    const float* x  = (const float*)d_in[0];
    const float* Wq = (const float*)d_in[1];
    const float* Wk = (const float*)d_in[2];
    const float* Wv = (const float*)d_in[3];
    const float* Wo = (const float*)d_in[4];
    const float* bo = (const float*)d_in[5];
    float* out = (float*)d_out;

    float *qb, *kb, *vb, *cb, *xt, *wt;
    cudaGetSymbolAddress((void**)&qb, g_q);
    cudaGetSymbolAddress((void**)&kb, g_k);
    cudaGetSymbolAddress((void**)&vb, g_v);
    cudaGetSymbolAddress((void**)&cb, g_ctx);
    cudaGetSymbolAddress((void**)&xt, g_xt);
    cudaGetSymbolAddress((void**)&wt, g_wt);
    float* wtq = wt + 0ULL * EMB * EMB;
    float* wtk = wt + 1ULL * EMB * EMB;
    float* wtv = wt + 2ULL * EMB * EMB;
    float* wto = wt + 3ULL * EMB * EMB;

    cudaFuncSetAttribute(gemm_tc<0>, cudaFuncAttributeMaxDynamicSharedMemorySize, GK_SMEM);
    cudaFuncSetAttribute(gemm_tc<1>, cudaFuncAttributeMaxDynamicSharedMemorySize, GK_SMEM);

    cvt_tf32_k<<<(MROWS * EMB / 4) / 256, 256>>>(x, xt);

    dim3 tg(EMB / 32, EMB / 32);
    dim3 tb(32, 8);
    transpose_k<<<tg, tb>>>(Wq, wtq);
    transpose_k<<<tg, tb>>>(Wk, wtk);
    transpose_k<<<tg, tb>>>(Wv, wtv);
    transpose_k<<<tg, tb>>>(Wo, wto);

    dim3 gg(EMB / 128, MROWS / 128);  // (8, 32)
    gemm_tc<1><<<gg, 256, GK_SMEM>>>(xt, wtq, nullptr, qb);
    gemm_tc<1><<<gg, 256, GK_SMEM>>>(xt, wtk, nullptr, kb);
    gemm_tc<1><<<gg, 256, GK_SMEM>>>(xt, wtv, nullptr, vb);

    flash_k<<<dim3(S_LEN / 128, BATCH * NH), 128>>>(qb, kb, vb, cb);

    gemm_tc<0><<<gg, 256, GK_SMEM>>>(cb, wto, bo, out);
}

// round 15
// speedup vs baseline: 2.8969x; 2.1926x over previous
#include <cuda_runtime.h>
#include <cuda_bf16.h>
#include <cstdint>
#include <cstddef>

// Problem constants
#define S_LEN  2048
#define EMB    1024
#define NH     16
#define HD     64
#define BATCH  2
#define MROWS  (BATCH * S_LEN)   // 4096

// Scratch in device globals (no allocation allowed)
__device__ float g_q[(size_t)BATCH * NH * S_LEN * HD];
__device__ float g_k[(size_t)BATCH * NH * S_LEN * HD];
__device__ float g_v[(size_t)BATCH * NH * S_LEN * HD];
__device__ float g_ctx[(size_t)BATCH * S_LEN * EMB];
__device__ float g_xt[(size_t)MROWS * EMB];       // x, tf32-rounded
__device__ float g_wt[4ULL * EMB * EMB];          // transposed weights, tf32-rounded

// ---------------------------------------------------------------------------
// Helpers
// ---------------------------------------------------------------------------
__device__ __forceinline__ uint32_t smem_u32(const void* p) {
    uint32_t a;
    asm("{ .reg .u64 t; cvta.to.shared.u64 t, %1; cvt.u32.u64 %0, t; }" : "=r"(a) : "l"(p));
    return a;
}
__device__ __forceinline__ float to_tf32(float x) {
    float y;
    asm("cvt.rna.tf32.f32 %0, %1;" : "=f"(y) : "f"(x));
    return y;
}

#define CP_ASYNC16(sa, gp) \
    asm volatile("cp.async.cg.shared.global [%0], [%1], 16;" :: "r"(sa), "l"(gp) : "memory")
#define CP_COMMIT() asm volatile("cp.async.commit_group;" ::: "memory")
#define CP_WAIT(n)  asm volatile("cp.async.wait_group %0;" :: "n"(n) : "memory")

// m16n8k8 tf32 mma: D += A * B  (A row-major m16k8 frag, B col-major n8k8 frag)
__device__ __forceinline__ void mma1688(float* c, const uint32_t* a, const uint32_t* b) {
    asm volatile(
        "mma.sync.aligned.m16n8k8.row.col.f32.tf32.tf32.f32 "
        "{%0,%1,%2,%3}, {%4,%5,%6,%7}, {%8,%9}, {%0,%1,%2,%3};"
        : "+f"(c[0]), "+f"(c[1]), "+f"(c[2]), "+f"(c[3])
        : "r"(a[0]), "r"(a[1]), "r"(a[2]), "r"(a[3]), "r"(b[0]), "r"(b[1]));
}

// ---------------------------------------------------------------------------
// x -> tf32-rounded copy (one-shot, 4M elements)
// ---------------------------------------------------------------------------
__global__ __launch_bounds__(256) void cvt_tf32_k(const float* __restrict__ in,
                                                  float* __restrict__ out)
{
    int i = blockIdx.x * 256 + threadIdx.x;
    float4 v = ((const float4*)in)[i];
    v.x = to_tf32(v.x); v.y = to_tf32(v.y);
    v.z = to_tf32(v.z); v.w = to_tf32(v.w);
    ((float4*)out)[i] = v;
}

// ---------------------------------------------------------------------------
// Weight transpose: WT[n][k] = tf32(W[k][n]); 1024x1024
// ---------------------------------------------------------------------------
__global__ __launch_bounds__(256) void transpose_k(const float* __restrict__ W,
                                                   float* __restrict__ WT)
{
    __shared__ float t[32][33];
    const int bx = blockIdx.x * 32, by = blockIdx.y * 32;
#pragma unroll
    for (int i = threadIdx.y; i < 32; i += 8)
        t[i][threadIdx.x] = W[(size_t)(by + i) * EMB + bx + threadIdx.x];
    __syncthreads();
#pragma unroll
    for (int i = threadIdx.y; i < 32; i += 8)
        WT[(size_t)(bx + i) * EMB + by + threadIdx.x] = to_tf32(t[threadIdx.x][i]);
}

// ---------------------------------------------------------------------------
// mma.sync tf32 GEMM: C[M,N] = A[M,K] @ BT[N,K]^T, all inputs pre-rounded tf32.
// CTA 128x128, BK=32, 256 threads (8 warps 2x4), warp tile 64x32.
// MODE 0: C[row*N+col] = acc + bias[col]
// MODE 1: headsplit write to [B, H, S, D], tf32-rounded (feeds flash mma)
// ---------------------------------------------------------------------------
#define GK_STRIDE 36
#define GK_TILE   (128 * GK_STRIDE * 4)
#define GK_SMEM   (4 * GK_TILE)

template <int MODE>
__global__ __launch_bounds__(256, 1) void gemm_tc(const float* __restrict__ A,
                                                  const float* __restrict__ BT,
                                                  const float* __restrict__ bias,
                                                  float* __restrict__ C)
{
    extern __shared__ char smem[];
    const uint32_t smem_base = smem_u32(smem);
    const int tid = threadIdx.x;
    const int wid = tid >> 5;
    const int lane = tid & 31;
    const int grp = lane >> 2;
    const int tig = lane & 3;
    const int bm = blockIdx.y * 128;
    const int bn = blockIdx.x * 128;
    const int wm = (wid >> 2) * 64;
    const int wn = (wid & 3) * 32;

    float acc[4][4][4];
#pragma unroll
    for (int mi = 0; mi < 4; mi++)
#pragma unroll
        for (int ni = 0; ni < 4; ni++)
#pragma unroll
            for (int r = 0; r < 4; r++) acc[mi][ni][r] = 0.f;

    const int crow = tid >> 1;
    const int cq   = (tid & 1) << 1;

    auto prefetch = [&](int c) {
        const int k0 = c * 32;
        const uint32_t sa = smem_base + (uint32_t)(c & 1) * GK_TILE;
        const uint32_t sb = smem_base + (uint32_t)(2 + (c & 1)) * GK_TILE;
#pragma unroll
        for (int h = 0; h < 2; h++) {
            int q0 = cq + h * 4;
            CP_ASYNC16(sa + (uint32_t)(crow * GK_STRIDE + q0 * 4) * 4,
                       A + (size_t)(bm + crow) * EMB + k0 + q0 * 4);
            CP_ASYNC16(sa + (uint32_t)(crow * GK_STRIDE + (q0 + 1) * 4) * 4,
                       A + (size_t)(bm + crow) * EMB + k0 + (q0 + 1) * 4);
        }
#pragma unroll
        for (int h = 0; h < 2; h++) {
            int q0 = cq + h * 4;
            CP_ASYNC16(sb + (uint32_t)(crow * GK_STRIDE + q0 * 4) * 4,
                       BT + (size_t)(bn + crow) * EMB + k0 + q0 * 4);
            CP_ASYNC16(sb + (uint32_t)(crow * GK_STRIDE + (q0 + 1) * 4) * 4,
                       BT + (size_t)(bn + crow) * EMB + k0 + (q0 + 1) * 4);
        }
        CP_COMMIT();
    };

    prefetch(0);

    for (int c = 0; c < 32; ++c) {
        if (c < 31) { prefetch(c + 1); CP_WAIT(1); }
        else        { CP_WAIT(0); }
        __syncthreads();

        const float* as = (const float*)(smem + (size_t)(c & 1) * GK_TILE);
        const float* bs = (const float*)(smem + (size_t)(2 + (c & 1)) * GK_TILE);

#pragma unroll
        for (int kk = 0; kk < 4; kk++) {
            const int kc = kk * 8 + tig;
            uint32_t af[4][4], bf[4][2];
#pragma unroll
            for (int mi = 0; mi < 4; mi++) {
                const float* p = as + (wm + mi * 16 + grp) * GK_STRIDE + kc;
                af[mi][0] = __float_as_uint(p[0]);
                af[mi][1] = __float_as_uint(p[8 * GK_STRIDE]);
                af[mi][2] = __float_as_uint(p[4]);
                af[mi][3] = __float_as_uint(p[8 * GK_STRIDE + 4]);
            }
#pragma unroll
            for (int ni = 0; ni < 4; ni++) {
                const float* p = bs + (wn + ni * 8 + grp) * GK_STRIDE + kc;
                bf[ni][0] = __float_as_uint(p[0]);
                bf[ni][1] = __float_as_uint(p[4]);
            }
#pragma unroll
            for (int mi = 0; mi < 4; mi++)
#pragma unroll
                for (int ni = 0; ni < 4; ni++)
                    mma1688(acc[mi][ni], af[mi], bf[ni]);
        }
        __syncthreads();
    }

#pragma unroll
    for (int mi = 0; mi < 4; mi++) {
#pragma unroll
        for (int half = 0; half < 2; half++) {
            const int row = bm + wm + mi * 16 + grp + half * 8;
            if (MODE == 0) {
#pragma unroll
                for (int ni = 0; ni < 4; ni++) {
                    const int col = bn + wn + ni * 8 + tig * 2;
                    float2 v;
                    v.x = acc[mi][ni][half * 2 + 0] + bias[col + 0];
                    v.y = acc[mi][ni][half * 2 + 1] + bias[col + 1];
                    *(float2*)&C[(size_t)row * EMB + col] = v;
                }
            } else {
                const int b_ = row >> 11;
                const int sr = row & (S_LEN - 1);
#pragma unroll
                for (int ni = 0; ni < 4; ni++) {
                    const int col = bn + wn + ni * 8 + tig * 2;
                    const int h = col >> 6;
                    const int d = col & (HD - 1);
                    float2 v;
                    v.x = to_tf32(acc[mi][ni][half * 2 + 0]);
                    v.y = to_tf32(acc[mi][ni][half * 2 + 1]);
                    *(float2*)(C + ((((size_t)b_ * NH + h) * S_LEN) + sr) * HD + d) = v;
                }
            }
        }
    }
}

// ---------------------------------------------------------------------------
// Tensor-core flash attention (causal), tf32 mma.sync.
// Block: 64 q-rows, 4 warps (16 q-rows each), 128 threads.
// Key tiles of 64, cp.async double-buffered K/V. Online softmax on C-frags.
// grid = (S/64, B*H)
// ---------------------------------------------------------------------------
#define FS        68                     // smem row stride in floats
#define FH_VS_OFF (2 * 64 * FS)          // after 2 K stages
#define FH_PS_OFF (4 * 64 * FS)          // after 2 V stages
#define FH_SMEM_BYTES ((FH_PS_OFF + 64 * FS) * 4)   // 87040

__global__ __launch_bounds__(128, 1) void flash_tc(const float* __restrict__ Q,
                                                   const float* __restrict__ Kg,
                                                   const float* __restrict__ Vg,
                                                   float* __restrict__ O)
{
    extern __shared__ float sm[];
    float* Ksm = sm;
    float* Vsm = sm + FH_VS_OFF;
    float* Psm = sm + FH_PS_OFF;   // also Q staging

    const int tid = threadIdx.x;
    const int wid = tid >> 5;
    const int lane = tid & 31;
    const int grp = lane >> 2;
    const int tig = lane & 3;
    const int qb = blockIdx.x;     // 0..31
    const int bh = blockIdx.y;     // 0..31

    const float* Qg = Q + ((size_t)bh * S_LEN + qb * 64) * HD;
    const float* Kb = Kg + (size_t)bh * S_LEN * HD;
    const float* Vb = Vg + (size_t)bh * S_LEN * HD;

    // Stage Q (64x64) into Psm, pre-scaled by 1/sqrt(64)=0.125 (exact pow2)
    for (int i = tid; i < 64 * 16; i += 128) {
        int row = i >> 4, f4 = i & 15;
        float4 v = ((const float4*)(Qg + (size_t)row * HD))[f4];
        v.x *= 0.125f; v.y *= 0.125f; v.z *= 0.125f; v.w *= 0.125f;
        *(float4*)&Psm[row * FS + f4 * 4] = v;
    }
    __syncthreads();

    // Q fragments: 8 k-steps x 4 regs, resident for whole kernel
    uint32_t qf[8][4];
    {
        const float* qw = Psm + (wid * 16) * FS;
#pragma unroll
        for (int ks = 0; ks < 8; ks++) {
            qf[ks][0] = __float_as_uint(qw[grp * FS + ks * 8 + tig]);
            qf[ks][1] = __float_as_uint(qw[(grp + 8) * FS + ks * 8 + tig]);
            qf[ks][2] = __float_as_uint(qw[grp * FS + ks * 8 + tig + 4]);
            qf[ks][3] = __float_as_uint(qw[(grp + 8) * FS + ks * 8 + tig + 4]);
        }
    }
    __syncthreads();   // Psm now free for P tiles

    float acc[8][4];
#pragma unroll
    for (int n = 0; n < 8; n++)
#pragma unroll
        for (int r = 0; r < 4; r++) acc[n][r] = 0.f;
    float m_lo = -1e30f, m_hi = -1e30f, l_lo = 0.f, l_hi = 0.f;

    const int crow = tid >> 1;            // 0..63
    const int chf  = (tid & 1) * 8;       // float4 col base 0 or 8

    auto prefetch = [&](int kt) {
        const int st = kt & 1;
        const float* ksrc = Kb + (size_t)(kt * 64 + crow) * HD;
        const float* vsrc = Vb + (size_t)(kt * 64 + crow) * HD;
        uint32_t kd = smem_u32(Ksm + (size_t)st * 64 * FS + crow * FS);
        uint32_t vd = smem_u32(Vsm + (size_t)st * 64 * FS + crow * FS);
#pragma unroll
        for (int j = 0; j < 8; j++) {
            int f4 = chf + j;
            CP_ASYNC16(kd + (uint32_t)f4 * 16, ksrc + f4 * 4);
            CP_ASYNC16(vd + (uint32_t)f4 * 16, vsrc + f4 * 4);
        }
        CP_COMMIT();
    };

    const int nt = qb + 1;
    prefetch(0);

    for (int kt = 0; kt < nt; kt++) {
        if (kt + 1 < nt) { prefetch(kt + 1); CP_WAIT(1); }
        else             { CP_WAIT(0); }
        __syncthreads();

        const float* ks_ = Ksm + (size_t)(kt & 1) * 64 * FS;
        const float* vs_ = Vsm + (size_t)(kt & 1) * 64 * FS;

        // --- scores S = Q K^T (pre-scaled) ---
        float c[8][4];
#pragma unroll
        for (int n = 0; n < 8; n++) {
#pragma unroll
            for (int r = 0; r < 4; r++) c[n][r] = 0.f;
            const float* kp = ks_ + (n * 8 + grp) * FS;
#pragma unroll
            for (int ks = 0; ks < 8; ks++) {
                uint32_t bf[2];
                bf[0] = __float_as_uint(kp[ks * 8 + tig]);
                bf[1] = __float_as_uint(kp[ks * 8 + tig + 4]);
                mma1688(c[n], qf[ks], bf);
            }
        }

        // --- causal mask (diagonal block only) ---
        if (kt == qb) {
            const int r0 = wid * 16 + grp, r1 = r0 + 8;
#pragma unroll
            for (int n = 0; n < 8; n++) {
                const int cl = n * 8 + 2 * tig;
                if (cl     > r0) c[n][0] = -1e30f;
                if (cl + 1 > r0) c[n][1] = -1e30f;
                if (cl     > r1) c[n][2] = -1e30f;
                if (cl + 1 > r1) c[n][3] = -1e30f;
            }
        }

        // --- online softmax ---
        float tmx_lo = -1e30f, tmx_hi = -1e30f;
#pragma unroll
        for (int n = 0; n < 8; n++) {
            tmx_lo = fmaxf(tmx_lo, fmaxf(c[n][0], c[n][1]));
            tmx_hi = fmaxf(tmx_hi, fmaxf(c[n][2], c[n][3]));
        }
        tmx_lo = fmaxf(tmx_lo, __shfl_xor_sync(0xFFFFFFFF, tmx_lo, 1));
        tmx_lo = fmaxf(tmx_lo, __shfl_xor_sync(0xFFFFFFFF, tmx_lo, 2));
        tmx_hi = fmaxf(tmx_hi, __shfl_xor_sync(0xFFFFFFFF, tmx_hi, 1));
        tmx_hi = fmaxf(tmx_hi, __shfl_xor_sync(0xFFFFFFFF, tmx_hi, 2));

        const float mn_lo = fmaxf(m_lo, tmx_lo);
        const float mn_hi = fmaxf(m_hi, tmx_hi);
        const float corr_lo = __expf(m_lo - mn_lo);
        const float corr_hi = __expf(m_hi - mn_hi);

        float sum_lo = 0.f, sum_hi = 0.f;
#pragma unroll
        for (int n = 0; n < 8; n++) {
            c[n][0] = __expf(c[n][0] - mn_lo);
            c[n][1] = __expf(c[n][1] - mn_lo);
            c[n][2] = __expf(c[n][2] - mn_hi);
            c[n][3] = __expf(c[n][3] - mn_hi);
            sum_lo += c[n][0] + c[n][1];
            sum_hi += c[n][2] + c[n][3];
        }
        sum_lo += __shfl_xor_sync(0xFFFFFFFF, sum_lo, 1);
        sum_lo += __shfl_xor_sync(0xFFFFFFFF, sum_lo, 2);
        sum_hi += __shfl_xor_sync(0xFFFFFFFF, sum_hi, 1);
        sum_hi += __shfl_xor_sync(0xFFFFFFFF, sum_hi, 2);

        l_lo = l_lo * corr_lo + sum_lo;
        l_hi = l_hi * corr_hi + sum_hi;
        m_lo = mn_lo; m_hi = mn_hi;

#pragma unroll
        for (int n = 0; n < 8; n++) {
            acc[n][0] *= corr_lo; acc[n][1] *= corr_lo;
            acc[n][2] *= corr_hi; acc[n][3] *= corr_hi;
        }

        // --- P -> per-warp SMEM (tf32-rounded), reload as A-frags ---
        float* pw = Psm + wid * 16 * FS;
#pragma unroll
        for (int n = 0; n < 8; n++) {
            float2 lo, hi;
            lo.x = to_tf32(c[n][0]); lo.y = to_tf32(c[n][1]);
            hi.x = to_tf32(c[n][2]); hi.y = to_tf32(c[n][3]);
            *(float2*)&pw[grp * FS + n * 8 + 2 * tig] = lo;
            *(float2*)&pw[(grp + 8) * FS + n * 8 + 2 * tig] = hi;
        }
        __syncwarp();

        // --- PV: acc += P @ V ---
#pragma unroll
        for (int ks = 0; ks < 8; ks++) {
            uint32_t pa[4];
            pa[0] = __float_as_uint(pw[grp * FS + ks * 8 + tig]);
            pa[1] = __float_as_uint(pw[(grp + 8) * FS + ks * 8 + tig]);
            pa[2] = __float_as_uint(pw[grp * FS + ks * 8 + tig + 4]);
            pa[3] = __float_as_uint(pw[(grp + 8) * FS + ks * 8 + tig + 4]);
            const float* v0 = vs_ + (ks * 8 + tig) * FS;
            const float* v1 = vs_ + (ks * 8 + tig + 4) * FS;
#pragma unroll
            for (int nd = 0; nd < 8; nd++) {
                uint32_t bf[2];
                bf[0] = __float_as_uint(v0[nd * 8 + grp]);
                bf[1] = __float_as_uint(v1[nd * 8 + grp]);
                mma1688(acc[nd], pa, bf);
            }
        }
        __syncthreads();
    }

    // --- epilogue: normalize, write ctx [B,S,E] tf32-rounded ---
    const float inv_lo = 1.f / l_lo;
    const float inv_hi = 1.f / l_hi;
    const int b_ = bh >> 4;
    const int h  = bh & 15;
    const int r_lo = qb * 64 + wid * 16 + grp;
    const int r_hi = r_lo + 8;
    float* olo = O + ((size_t)b_ * S_LEN + r_lo) * EMB + h * HD;
    float* ohi = O + ((size_t)b_ * S_LEN + r_hi) * EMB + h * HD;
#pragma unroll
    for (int nd = 0; nd < 8; nd++) {
        const int col = nd * 8 + 2 * tig;
        float2 v;
        v.x = to_tf32(acc[nd][0] * inv_lo);
        v.y = to_tf32(acc[nd][1] * inv_lo);
        *(float2*)(olo + col) = v;
        v.x = to_tf32(acc[nd][2] * inv_hi);
        v.y = to_tf32(acc[nd][3] * inv_hi);
        *(float2*)(ohi + col) = v;
    }
}

// ---------------------------------------------------------------------------
extern "C" void kernel_launch(void* const* d_in, const int* in_sizes, int n_in,
                              void* d_out, int out_size)
{
    const float* x  = (const float*)d_in[0];
    const float* Wq = (const float*)d_in[1];
    const float* Wk = (const float*)d_in[2];
    const float* Wv = (const float*)d_in[3];
    const float* Wo = (const float*)d_in[4];
    const float* bo = (const float*)d_in[5];
    float* out = (float*)d_out;

    float *qb, *kb, *vb, *cb, *xt, *wt;
    cudaGetSymbolAddress((void**)&qb, g_q);
    cudaGetSymbolAddress((void**)&kb, g_k);
    cudaGetSymbolAddress((void**)&vb, g_v);
    cudaGetSymbolAddress((void**)&cb, g_ctx);
    cudaGetSymbolAddress((void**)&xt, g_xt);
    cudaGetSymbolAddress((void**)&wt, g_wt);
    float* wtq = wt + 0ULL * EMB * EMB;
    float* wtk = wt + 1ULL * EMB * EMB;
    float* wtv = wt + 2ULL * EMB * EMB;
    float* wto = wt + 3ULL * EMB * EMB;

    cudaFuncSetAttribute(gemm_tc<0>, cudaFuncAttributeMaxDynamicSharedMemorySize, GK_SMEM);
    cudaFuncSetAttribute(gemm_tc<1>, cudaFuncAttributeMaxDynamicSharedMemorySize, GK_SMEM);
    cudaFuncSetAttribute(flash_tc, cudaFuncAttributeMaxDynamicSharedMemorySize, FH_SMEM_BYTES);

    cvt_tf32_k<<<(MROWS * EMB / 4) / 256, 256>>>(x, xt);

    dim3 tg(EMB / 32, EMB / 32);
    dim3 tb(32, 8);
    transpose_k<<<tg, tb>>>(Wq, wtq);
    transpose_k<<<tg, tb>>>(Wk, wtk);
    transpose_k<<<tg, tb>>>(Wv, wtv);
    transpose_k<<<tg, tb>>>(Wo, wto);

    dim3 gg(EMB / 128, MROWS / 128);  // (8, 32)
    gemm_tc<1><<<gg, 256, GK_SMEM>>>(xt, wtq, nullptr, qb);
    gemm_tc<1><<<gg, 256, GK_SMEM>>>(xt, wtk, nullptr, kb);
    gemm_tc<1><<<gg, 256, GK_SMEM>>>(xt, wtv, nullptr, vb);

    flash_tc<<<dim3(S_LEN / 64, BATCH * NH), 128, FH_SMEM_BYTES>>>(qb, kb, vb, cb);

    gemm_tc<0><<<gg, 256, GK_SMEM>>>(cb, wto, bo, out);
}